// round 2
// baseline (speedup 1.0000x reference)
#include <cuda_runtime.h>
#include <cstdint>

// Problem constants (fixed by the dataset)
#define NN     50000      // nodes
#define DD     256        // feature dim
#define TWO_D  512
#define EE     320000     // edges

// Scratch: per-node projections. AB[n][0:256] = z[n]@W1a^T + b1 (A'),
//          AB[n][256:512] = z[n]@W1b^T (B). 102.4 MB static device array.
__device__ float g_AB[(size_t)NN * TWO_D];
// Repacked weights, K-major: g_Wt[k*512 + j] = W(j,k)
__device__ float g_Wt[DD * TWO_D];
// Edge-index dtype flag: 1 if buffer is int64, 0 if int32.
__device__ int g_idx_is64;

// ---------------------------------------------------------------------------
// Kernel -1: detect edge_index dtype. If int64 (values < 2^31), every odd
// 32-bit word of the buffer is 0. If int32, odd words are random indices.
// Samples 4096 odd words within the first 2*EE words (valid either way).
// ---------------------------------------------------------------------------
__global__ void detect_idx_kernel(const int* __restrict__ ei_words) {
    __shared__ int nz;
    if (threadIdx.x == 0) nz = 0;
    __syncthreads();
    // 4096 samples: thread t checks odd words at stride.
    int found = 0;
    for (int i = threadIdx.x; i < 4096; i += blockDim.x) {
        int pos = 2 * (i * (EE / 4096)) + 1;   // odd word, spread over buffer
        if (ei_words[pos] != 0) found = 1;
    }
    if (found) atomicOr(&nz, 1);
    __syncthreads();
    if (threadIdx.x == 0) g_idx_is64 = (nz == 0) ? 1 : 0;
}

// ---------------------------------------------------------------------------
// Kernel 0: repack w1 into K-major layout for coalesced GEMM B-tile loads.
// ---------------------------------------------------------------------------
__global__ void repack_kernel(const float* __restrict__ w1) {
    int idx = blockIdx.x * blockDim.x + threadIdx.x;  // idx = k*512 + j
    if (idx < DD * TWO_D) {
        int k = idx >> 9;
        int j = idx & 511;
        float v = (j < DD) ? w1[j * TWO_D + k]
                           : w1[(j - DD) * TWO_D + DD + k];
        g_Wt[idx] = v;
    }
}

// ---------------------------------------------------------------------------
// Kernel 1: fp32 SIMT GEMM  C[50000, 512] = z[50000, 256] @ Wt[256, 512]
// Tile BM=128, BN=128, BK=16; 256 threads; 8x8 register blocking.
// ---------------------------------------------------------------------------
#define BM 128
#define BN 128
#define BK 16

__global__ __launch_bounds__(256, 2)
void node_gemm_kernel(const float* __restrict__ z, const float* __restrict__ b1) {
    __shared__ float As[BK][BM + 4];   // transposed A tile: As[k][m]
    __shared__ float Bs[BK][BN + 4];

    const int m0 = blockIdx.x * BM;
    const int j0 = blockIdx.y * BN;   // 0,128,256,384
    const int t  = threadIdx.x;
    const int tx = t & 15;            // column group (8 cols each)
    const int ty = t >> 4;            // row group    (8 rows each)

    float acc[8][8];
    #pragma unroll
    for (int i = 0; i < 8; i++)
        #pragma unroll
        for (int j = 0; j < 8; j++) acc[i][j] = 0.f;

    for (int k0 = 0; k0 < DD; k0 += BK) {
        #pragma unroll
        for (int l = 0; l < 2; l++) {
            int f   = t + l * 256;
            int row = f >> 2;
            int c   = f & 3;
            int gr  = m0 + row;
            float4 v = make_float4(0.f, 0.f, 0.f, 0.f);
            if (gr < NN)
                v = *(const float4*)(z + (size_t)gr * DD + k0 + c * 4);
            As[c * 4 + 0][row] = v.x;
            As[c * 4 + 1][row] = v.y;
            As[c * 4 + 2][row] = v.z;
            As[c * 4 + 3][row] = v.w;
        }
        #pragma unroll
        for (int l = 0; l < 2; l++) {
            int f  = t + l * 256;
            int kr = f >> 5;
            int c  = f & 31;
            float4 v = *(const float4*)(g_Wt + (size_t)(k0 + kr) * TWO_D + j0 + c * 4);
            *(float4*)&Bs[kr][c * 4] = v;
        }
        __syncthreads();

        #pragma unroll
        for (int kk = 0; kk < BK; kk++) {
            float ra[8], rb[8];
            float4 a01 = *(const float4*)&As[kk][ty * 8];
            float4 a23 = *(const float4*)&As[kk][ty * 8 + 4];
            float4 b01 = *(const float4*)&Bs[kk][tx * 8];
            float4 b23 = *(const float4*)&Bs[kk][tx * 8 + 4];
            ra[0]=a01.x; ra[1]=a01.y; ra[2]=a01.z; ra[3]=a01.w;
            ra[4]=a23.x; ra[5]=a23.y; ra[6]=a23.z; ra[7]=a23.w;
            rb[0]=b01.x; rb[1]=b01.y; rb[2]=b01.z; rb[3]=b01.w;
            rb[4]=b23.x; rb[5]=b23.y; rb[6]=b23.z; rb[7]=b23.w;
            #pragma unroll
            for (int i = 0; i < 8; i++)
                #pragma unroll
                for (int j = 0; j < 8; j++)
                    acc[i][j] += ra[i] * rb[j];
        }
        __syncthreads();
    }

    const bool add_b1 = (j0 < DD);
    float bb[8];
    #pragma unroll
    for (int u = 0; u < 8; u++)
        bb[u] = add_b1 ? b1[j0 + tx * 8 + u] : 0.f;

    #pragma unroll
    for (int i = 0; i < 8; i++) {
        int gr = m0 + ty * 8 + i;
        if (gr < NN) {
            float* dst = g_AB + (size_t)gr * TWO_D + j0 + tx * 8;
            float4 v0, v1;
            v0.x = acc[i][0] + bb[0]; v0.y = acc[i][1] + bb[1];
            v0.z = acc[i][2] + bb[2]; v0.w = acc[i][3] + bb[3];
            v1.x = acc[i][4] + bb[4]; v1.y = acc[i][5] + bb[5];
            v1.z = acc[i][6] + bb[6]; v1.w = acc[i][7] + bb[7];
            *(float4*)(dst)     = v0;
            *(float4*)(dst + 4) = v1;
        }
    }
}

// ---------------------------------------------------------------------------
// Kernel 2: per-edge reduction. One warp per edge (grid-stride):
//   out[e] = sum_d w2[d] * relu(A'[src][d] + B[dst][d]) + b2
// Handles both int32 and int64 edge_index via the detected flag.
// ---------------------------------------------------------------------------
__global__ __launch_bounds__(256)
void edge_kernel(const void* __restrict__ ei_raw,
                 const float* __restrict__ w2,
                 const float* __restrict__ b2,
                 float* __restrict__ out) {
    const int lane   = threadIdx.x & 31;
    const int warp   = (blockIdx.x * blockDim.x + threadIdx.x) >> 5;
    const int nwarps = (gridDim.x * blockDim.x) >> 5;
    const int is64   = g_idx_is64;

    const float4 w2a = __ldg((const float4*)w2 + lane);       // d = 4*lane..
    const float4 w2b = __ldg((const float4*)w2 + 32 + lane);  // d = 128+4*lane..
    const float  b2v = __ldg(b2);

    const int*       ei32 = (const int*)ei_raw;
    const long long* ei64 = (const long long*)ei_raw;

    for (int e = warp; e < EE; e += nwarps) {
        int s, d;
        if (is64) {
            s = (int)ei64[e];
            d = (int)ei64[EE + e];
        } else {
            s = ei32[e];
            d = ei32[EE + e];
        }
        const float4* Ap = (const float4*)(g_AB + (size_t)s * TWO_D);       // A'
        const float4* Bp = (const float4*)(g_AB + (size_t)d * TWO_D + DD);  // B
        float4 a0 = __ldg(Ap + lane);
        float4 a1 = __ldg(Ap + 32 + lane);
        float4 c0 = __ldg(Bp + lane);
        float4 c1 = __ldg(Bp + 32 + lane);

        float acc;
        acc  = w2a.x * fmaxf(a0.x + c0.x, 0.f);
        acc += w2a.y * fmaxf(a0.y + c0.y, 0.f);
        acc += w2a.z * fmaxf(a0.z + c0.z, 0.f);
        acc += w2a.w * fmaxf(a0.w + c0.w, 0.f);
        acc += w2b.x * fmaxf(a1.x + c1.x, 0.f);
        acc += w2b.y * fmaxf(a1.y + c1.y, 0.f);
        acc += w2b.z * fmaxf(a1.z + c1.z, 0.f);
        acc += w2b.w * fmaxf(a1.w + c1.w, 0.f);

        #pragma unroll
        for (int o = 16; o > 0; o >>= 1)
            acc += __shfl_xor_sync(0xFFFFFFFFu, acc, o);

        if (lane == 0) out[e] = acc + b2v;
    }
}

// ---------------------------------------------------------------------------
extern "C" void kernel_launch(void* const* d_in, const int* in_sizes, int n_in,
                              void* d_out, int out_size) {
    const float* z  = (const float*)d_in[0];
    const void*  ei = d_in[1];
    const float* w1 = (const float*)d_in[2];
    const float* b1 = (const float*)d_in[3];
    const float* w2 = (const float*)d_in[4];
    const float* b2 = (const float*)d_in[5];
    float*       out = (float*)d_out;

    // -1) detect edge_index dtype (int32 vs int64)
    detect_idx_kernel<<<1, 256>>>((const int*)ei);

    // 0) repack weights (131072 elems)
    repack_kernel<<<(DD * TWO_D + 255) / 256, 256>>>(w1);

    // 1) node GEMM: grid (ceil(50000/128)=391, 512/128=4)
    dim3 ggrid((NN + BM - 1) / BM, TWO_D / BN);
    node_gemm_kernel<<<ggrid, 256>>>(z, b1);

    // 2) edge reduction: grid-stride, 2048 blocks x 8 warps
    edge_kernel<<<2048, 256>>>(ei, w2, b2, out);
}

// round 4
// speedup vs baseline: 1.9184x; 1.9184x over previous
#include <cuda_runtime.h>
#include <cuda_bf16.h>
#include <cstdint>

// Problem constants (fixed by the dataset)
#define NN     50000
#define DD     256
#define TWO_D  512
#define EE     320000

// ---------------------------------------------------------------------------
// Scratch (static device arrays; no allocation allowed)
// ---------------------------------------------------------------------------
__device__ float g_AB[(size_t)NN * TWO_D];          // per-node A'|B projections
__device__ __nv_bfloat16 g_zh[(size_t)NN * DD];     // z hi split   [n][k]
__device__ __nv_bfloat16 g_zl[(size_t)NN * DD];     // z lo split
__device__ __nv_bfloat16 g_wh[(size_t)TWO_D * DD];  // W hi split   [j][k]
__device__ __nv_bfloat16 g_wl[(size_t)TWO_D * DD];  // W lo split
__device__ int g_idx_is64;

// ---------------------------------------------------------------------------
// Prep kernels
// ---------------------------------------------------------------------------
__global__ void detect_idx_kernel(const int* __restrict__ ei_words) {
    __shared__ int nz;
    if (threadIdx.x == 0) nz = 0;
    __syncthreads();
    int found = 0;
    for (int i = threadIdx.x; i < 4096; i += blockDim.x) {
        int pos = 2 * (i * (EE / 4096)) + 1;
        if (ei_words[pos] != 0) found = 1;
    }
    if (found) atomicOr(&nz, 1);
    __syncthreads();
    if (threadIdx.x == 0) g_idx_is64 = (nz == 0) ? 1 : 0;
}

__global__ void convert_z_kernel(const float* __restrict__ z) {
    int stride = gridDim.x * blockDim.x;
    for (int i = blockIdx.x * blockDim.x + threadIdx.x; i < NN * DD; i += stride) {
        float v = z[i];
        __nv_bfloat16 h = __float2bfloat16_rn(v);
        g_zh[i] = h;
        g_zl[i] = __float2bfloat16_rn(v - __bfloat162float(h));
    }
}

// W[j][k]: j<256 -> w1[j*512+k]; j>=256 -> w1[(j-256)*512+256+k]
__global__ void convert_w_kernel(const float* __restrict__ w1) {
    int idx = blockIdx.x * blockDim.x + threadIdx.x;  // idx = j*256 + k
    if (idx < TWO_D * DD) {
        int j = idx >> 8;
        int k = idx & 255;
        float v = (j < DD) ? w1[j * TWO_D + k] : w1[(j - DD) * TWO_D + DD + k];
        __nv_bfloat16 h = __float2bfloat16_rn(v);
        g_wh[idx] = h;
        g_wl[idx] = __float2bfloat16_rn(v - __bfloat162float(h));
    }
}

// ---------------------------------------------------------------------------
// mma.sync helpers (sm_80+, target-independent; no tcgen05!)
// ---------------------------------------------------------------------------
__device__ __forceinline__ uint32_t smem_u32(const void* p) {
    uint32_t a;
    asm("{ .reg .u64 t; cvta.to.shared.u64 t, %1; cvt.u32.u64 %0, t; }" : "=r"(a) : "l"(p));
    return a;
}
__device__ __forceinline__ void ldm4(uint32_t* r, uint32_t addr) {
    asm volatile("ldmatrix.sync.aligned.m8n8.x4.shared.b16 {%0,%1,%2,%3}, [%4];"
                 : "=r"(r[0]), "=r"(r[1]), "=r"(r[2]), "=r"(r[3]) : "r"(addr));
}
__device__ __forceinline__ void mma16816(float* c, const uint32_t* a, uint32_t b0, uint32_t b1) {
    asm volatile("mma.sync.aligned.m16n8k16.row.col.f32.bf16.bf16.f32 "
                 "{%0,%1,%2,%3}, {%4,%5,%6,%7}, {%8,%9}, {%0,%1,%2,%3};"
                 : "+f"(c[0]), "+f"(c[1]), "+f"(c[2]), "+f"(c[3])
                 : "r"(a[0]), "r"(a[1]), "r"(a[2]), "r"(a[3]), "r"(b0), "r"(b1));
}
__device__ __forceinline__ void cp16(uint32_t dst, const void* src) {
    asm volatile("cp.async.cg.shared.global [%0], [%1], 16;" :: "r"(dst), "l"(src));
}

// Row layout: 128 bytes/row (= 64 bf16: [hi split 32 | lo split 32]).
// Swizzled byte offset for (row, 16B-chunk c in 0..7):
//   off = row*128 + 16*(c ^ (row & 7))  -> conflict-free ldmatrix.
__device__ __forceinline__ uint32_t tile_off(int row, int c) {
    return row * 128 + ((c ^ (row & 7)) << 4);
}
// ldmatrix.x4 thread address within a tile: covers rows m..m+15, chunks c8, c8+1.
__device__ __forceinline__ uint32_t ldm_addr(uint32_t base, int m, int c8, int lane) {
    int g = lane >> 3;
    int row = m + (lane & 7) + ((g & 1) << 3);
    int c = c8 + (g >> 1);
    return base + tile_off(row, c);
}

// ---------------------------------------------------------------------------
// Node GEMM via mma.sync:  g_AB[50000,512] = z @ W^T (+ b1 on cols 0..255)
// CTA 128x128, BK=32, 8 warps (2 x 4), warp tile 64x32.
// 3-pass split accumulation in fp32: Ah*Bh + Ah*Bl + Al*Bh.
// SMEM: A stages @ 0,16K; B stages @ 32K,48K. 64 KB dynamic.
// ---------------------------------------------------------------------------
#define SM_GEMM_TOTAL 65536

__device__ __forceinline__ void load_stage(uint32_t sbase, int st, int kc,
                                           int m0, int j0, int tid) {
    const char* zh = (const char*)g_zh;
    const char* zl = (const char*)g_zl;
    const char* wh = (const char*)g_wh;
    const char* wl = (const char*)g_wl;
    uint32_t Ab = sbase + st * 16384;
    uint32_t Bb = sbase + 32768 + st * 16384;
    #pragma unroll
    for (int i = 0; i < 8; i++) {
        int cid = tid + i * 256;          // 0..2047
        if (cid < 1024) {                 // A: row r, chunk sub
            int r = cid >> 3, sub = cid & 7;
            int gr = m0 + r; if (gr >= NN) gr = NN - 1;
            const char* src = (sub < 4)
                ? zh + (size_t)gr * 512 + kc * 64 + sub * 16
                : zl + (size_t)gr * 512 + kc * 64 + (sub - 4) * 16;
            cp16(Ab + tile_off(r, sub), src);
        } else {                          // B
            int c = cid - 1024;
            int r = c >> 3, sub = c & 7;
            int gj = j0 + r;
            const char* src = (sub < 4)
                ? wh + (size_t)gj * 512 + kc * 64 + sub * 16
                : wl + (size_t)gj * 512 + kc * 64 + (sub - 4) * 16;
            cp16(Bb + tile_off(r, sub), src);
        }
    }
    asm volatile("cp.async.commit_group;" ::: "memory");
}

__global__ __launch_bounds__(256)
void node_gemm_mma(const float* __restrict__ b1) {
    extern __shared__ __align__(128) char smem[];
    const uint32_t sbase = smem_u32(smem);
    const int tid  = threadIdx.x;
    const int lane = tid & 31;
    const int wid  = tid >> 5;
    const int wm   = wid >> 2;        // 0..1  (64 rows each)
    const int wn   = wid & 3;         // 0..3  (32 cols each)
    const int m0   = blockIdx.x * 128;
    const int j0   = blockIdx.y * 128;

    float acc[16][4];
    #pragma unroll
    for (int i = 0; i < 16; i++)
        #pragma unroll
        for (int q = 0; q < 4; q++) acc[i][q] = 0.f;

    load_stage(sbase, 0, 0, m0, j0, tid);

    #pragma unroll 1
    for (int kc = 0; kc < 8; kc++) {
        if (kc < 7) load_stage(sbase, (kc + 1) & 1, kc + 1, m0, j0, tid);
        if (kc < 7) asm volatile("cp.async.wait_group 1;" ::: "memory");
        else        asm volatile("cp.async.wait_group 0;" ::: "memory");
        __syncthreads();

        const int st = kc & 1;
        const uint32_t Ab = sbase + st * 16384;
        const uint32_t Bb = sbase + 32768 + st * 16384;

        #pragma unroll
        for (int kk = 0; kk < 2; kk++) {
            const int c8h = kk * 2;       // hi split chunks
            const int c8l = 4 + kk * 2;   // lo split chunks
            uint32_t ah[4][4], al[4][4], bh[2][4], bl[2][4];
            #pragma unroll
            for (int mt = 0; mt < 4; mt++) {
                ldm4(ah[mt], ldm_addr(Ab, wm * 64 + mt * 16, c8h, lane));
                ldm4(al[mt], ldm_addr(Ab, wm * 64 + mt * 16, c8l, lane));
            }
            #pragma unroll
            for (int q = 0; q < 2; q++) {
                ldm4(bh[q], ldm_addr(Bb, wn * 32 + q * 16, c8h, lane));
                ldm4(bl[q], ldm_addr(Bb, wn * 32 + q * 16, c8l, lane));
            }
            #pragma unroll
            for (int mt = 0; mt < 4; mt++)
                #pragma unroll
                for (int nt = 0; nt < 4; nt++) {
                    // n-tile nt: regs {r[nt&1], r[(nt&1)+2]} of quad nt>>1
                    uint32_t bh0 = bh[nt >> 1][nt & 1], bh1 = bh[nt >> 1][(nt & 1) + 2];
                    uint32_t bl0 = bl[nt >> 1][nt & 1], bl1 = bl[nt >> 1][(nt & 1) + 2];
                    float* cc = acc[mt * 4 + nt];
                    mma16816(cc, ah[mt], bh0, bh1);
                    mma16816(cc, ah[mt], bl0, bl1);
                    mma16816(cc, al[mt], bh0, bh1);
                }
        }
        __syncthreads();
    }

    // Epilogue: direct float2 stores (+ bias for cols < 256)
    const bool has_bias = (j0 < DD);
    #pragma unroll
    for (int nt = 0; nt < 4; nt++) {
        int colg = j0 + wn * 32 + nt * 8 + (lane & 3) * 2;
        float bv0 = 0.f, bv1 = 0.f;
        if (has_bias) { bv0 = __ldg(&b1[colg]); bv1 = __ldg(&b1[colg + 1]); }
        #pragma unroll
        for (int mt = 0; mt < 4; mt++) {
            float* cc = acc[mt * 4 + nt];
            int r0 = m0 + wm * 64 + mt * 16 + (lane >> 2);
            if (r0 < NN)
                *(float2*)(g_AB + (size_t)r0 * TWO_D + colg) =
                    make_float2(cc[0] + bv0, cc[1] + bv1);
            if (r0 + 8 < NN)
                *(float2*)(g_AB + (size_t)(r0 + 8) * TWO_D + colg) =
                    make_float2(cc[2] + bv0, cc[3] + bv1);
        }
    }
}

// ---------------------------------------------------------------------------
// Edge kernel: one warp per edge.
//   out[e] = sum_d w2[d] * relu(A'[src][d] + B[dst][d]) + b2
// ---------------------------------------------------------------------------
__global__ __launch_bounds__(256)
void edge_kernel(const void* __restrict__ ei_raw,
                 const float* __restrict__ w2,
                 const float* __restrict__ b2,
                 float* __restrict__ out) {
    const int lane   = threadIdx.x & 31;
    const int warp   = (blockIdx.x * blockDim.x + threadIdx.x) >> 5;
    const int nwarps = (gridDim.x * blockDim.x) >> 5;
    const int is64   = g_idx_is64;

    const float4 w2a = __ldg((const float4*)w2 + lane);
    const float4 w2b = __ldg((const float4*)w2 + 32 + lane);
    const float  b2v = __ldg(b2);

    const int*       ei32 = (const int*)ei_raw;
    const long long* ei64 = (const long long*)ei_raw;

    for (int e = warp; e < EE; e += nwarps) {
        int s, d;
        if (is64) { s = (int)ei64[e]; d = (int)ei64[EE + e]; }
        else      { s = ei32[e];      d = ei32[EE + e]; }
        const float4* Ap = (const float4*)(g_AB + (size_t)s * TWO_D);
        const float4* Bp = (const float4*)(g_AB + (size_t)d * TWO_D + DD);
        float4 a0 = __ldg(Ap + lane);
        float4 a1 = __ldg(Ap + 32 + lane);
        float4 c0 = __ldg(Bp + lane);
        float4 c1 = __ldg(Bp + 32 + lane);

        float acc;
        acc  = w2a.x * fmaxf(a0.x + c0.x, 0.f);
        acc += w2a.y * fmaxf(a0.y + c0.y, 0.f);
        acc += w2a.z * fmaxf(a0.z + c0.z, 0.f);
        acc += w2a.w * fmaxf(a0.w + c0.w, 0.f);
        acc += w2b.x * fmaxf(a1.x + c1.x, 0.f);
        acc += w2b.y * fmaxf(a1.y + c1.y, 0.f);
        acc += w2b.z * fmaxf(a1.z + c1.z, 0.f);
        acc += w2b.w * fmaxf(a1.w + c1.w, 0.f);

        #pragma unroll
        for (int o = 16; o > 0; o >>= 1)
            acc += __shfl_xor_sync(0xFFFFFFFFu, acc, o);

        if (lane == 0) out[e] = acc + b2v;
    }
}

// ---------------------------------------------------------------------------
extern "C" void kernel_launch(void* const* d_in, const int* in_sizes, int n_in,
                              void* d_out, int out_size) {
    const float* z  = (const float*)d_in[0];
    const void*  ei = d_in[1];
    const float* w1 = (const float*)d_in[2];
    const float* b1 = (const float*)d_in[3];
    const float* w2 = (const float*)d_in[4];
    const float* b2 = (const float*)d_in[5];
    float*       out = (float*)d_out;

    // Not a stream op; deterministic, called every time (no static guards).
    cudaFuncSetAttribute(node_gemm_mma, cudaFuncAttributeMaxDynamicSharedMemorySize,
                         SM_GEMM_TOTAL);

    detect_idx_kernel<<<1, 256>>>((const int*)ei);
    convert_z_kernel<<<4096, 256>>>(z);
    convert_w_kernel<<<(TWO_D * DD + 255) / 256, 256>>>(w1);

    dim3 ggrid((NN + 127) / 128, 4);   // 391 x 4
    node_gemm_mma<<<ggrid, 256, SM_GEMM_TOTAL>>>(b1);

    edge_kernel<<<2048, 256>>>(ei, w2, b2, out);
}

// round 5
// speedup vs baseline: 2.3262x; 1.2125x over previous
#include <cuda_runtime.h>
#include <cuda_bf16.h>
#include <cuda_fp16.h>
#include <cstdint>

// Problem constants (fixed by the dataset)
#define NN     50000
#define DD     256
#define TWO_D  512
#define EE     320000

// ---------------------------------------------------------------------------
// Scratch (static device arrays; no allocation allowed)
// ---------------------------------------------------------------------------
__device__ __half g_ABh[(size_t)NN * TWO_D];        // per-node A'|B in fp16
// Packed split layouts: [row][kchunk 0..7][hi 32 halves | lo 32 halves]
// = 512 bf16 per row = 1024 bytes, matching the SMEM tile row exactly.
__device__ __nv_bfloat16 g_zp[(size_t)NN * 512];
__device__ __nv_bfloat16 g_wp[(size_t)TWO_D * 512];
__device__ int g_idx_is64;

// ---------------------------------------------------------------------------
// Prep kernels
// ---------------------------------------------------------------------------
__global__ void detect_idx_kernel(const int* __restrict__ ei_words) {
    __shared__ int nz;
    if (threadIdx.x == 0) nz = 0;
    __syncthreads();
    int found = 0;
    for (int i = threadIdx.x; i < 4096; i += blockDim.x) {
        int pos = 2 * (i * (EE / 4096)) + 1;
        if (ei_words[pos] != 0) found = 1;
    }
    if (found) atomicOr(&nz, 1);
    __syncthreads();
    if (threadIdx.x == 0) g_idx_is64 = (nz == 0) ? 1 : 0;
}

__global__ void convert_z_kernel(const float* __restrict__ z) {
    int stride = gridDim.x * blockDim.x;
    for (int i = blockIdx.x * blockDim.x + threadIdx.x; i < NN * DD; i += stride) {
        int n = i >> 8, k = i & 255;
        float v = z[i];
        __nv_bfloat16 h = __float2bfloat16_rn(v);
        __nv_bfloat16 l = __float2bfloat16_rn(v - __bfloat162float(h));
        size_t base = (size_t)n * 512 + ((k >> 5) << 6) + (k & 31);
        g_zp[base]      = h;
        g_zp[base + 32] = l;
    }
}

// W[j][k]: j<256 -> w1[j*512+k]; j>=256 -> w1[(j-256)*512+256+k]
__global__ void convert_w_kernel(const float* __restrict__ w1) {
    int idx = blockIdx.x * blockDim.x + threadIdx.x;  // idx = j*256 + k
    if (idx < TWO_D * DD) {
        int j = idx >> 8;
        int k = idx & 255;
        float v = (j < DD) ? w1[j * TWO_D + k] : w1[(j - DD) * TWO_D + DD + k];
        __nv_bfloat16 h = __float2bfloat16_rn(v);
        __nv_bfloat16 l = __float2bfloat16_rn(v - __bfloat162float(h));
        size_t base = (size_t)j * 512 + ((k >> 5) << 6) + (k & 31);
        g_wp[base]      = h;
        g_wp[base + 32] = l;
    }
}

// ---------------------------------------------------------------------------
// mma.sync helpers (sm_80+, target-independent)
// ---------------------------------------------------------------------------
__device__ __forceinline__ uint32_t smem_u32(const void* p) {
    uint32_t a;
    asm("{ .reg .u64 t; cvta.to.shared.u64 t, %1; cvt.u32.u64 %0, t; }" : "=r"(a) : "l"(p));
    return a;
}
__device__ __forceinline__ void ldm4(uint32_t* r, uint32_t addr) {
    asm volatile("ldmatrix.sync.aligned.m8n8.x4.shared.b16 {%0,%1,%2,%3}, [%4];"
                 : "=r"(r[0]), "=r"(r[1]), "=r"(r[2]), "=r"(r[3]) : "r"(addr));
}
__device__ __forceinline__ void mma16816(float* c, const uint32_t* a, uint32_t b0, uint32_t b1) {
    asm volatile("mma.sync.aligned.m16n8k16.row.col.f32.bf16.bf16.f32 "
                 "{%0,%1,%2,%3}, {%4,%5,%6,%7}, {%8,%9}, {%0,%1,%2,%3};"
                 : "+f"(c[0]), "+f"(c[1]), "+f"(c[2]), "+f"(c[3])
                 : "r"(a[0]), "r"(a[1]), "r"(a[2]), "r"(a[3]), "r"(b0), "r"(b1));
}
__device__ __forceinline__ void cp16(uint32_t dst, const void* src) {
    asm volatile("cp.async.cg.shared.global [%0], [%1], 16;" :: "r"(dst), "l"(src));
}

// Row layout: 128 bytes/row (= 64 bf16: [hi 32 | lo 32]).
// Swizzled byte offset for (row, 16B-chunk c in 0..7).
__device__ __forceinline__ uint32_t tile_off(int row, int c) {
    return row * 128 + ((c ^ (row & 7)) << 4);
}
__device__ __forceinline__ uint32_t ldm_addr(uint32_t base, int m, int c8, int lane) {
    int g = lane >> 3;
    int row = m + (lane & 7) + ((g & 1) << 3);
    int c = c8 + (g >> 1);
    return base + tile_off(row, c);
}

// ---------------------------------------------------------------------------
// Node GEMM via mma.sync:  g_ABh[50000,512] = fp16(z @ W^T (+ b1 cols<256))
// CTA 128x128, BK=32/stage, 3-stage cp.async ring, 8 warps, warp tile 64x32.
// 3-pass bf16 split accumulation in fp32: Ah*Bh + Ah*Bl + Al*Bh.
// SMEM: A stages @ 0/16K/32K ; B stages @ 48K/64K/80K. Total 96 KB.
// ---------------------------------------------------------------------------
#define B_REGION 49152
#define SM_GEMM_TOTAL 98304

__global__ __launch_bounds__(256, 2)
void node_gemm_mma(const float* __restrict__ b1) {
    extern __shared__ __align__(128) char smem[];
    const uint32_t sbase = smem_u32(smem);
    const int tid  = threadIdx.x;
    const int lane = tid & 31;
    const int wid  = tid >> 5;
    const int wm   = wid >> 2;        // 0..1 (64 rows)
    const int wn   = wid & 3;         // 0..3 (32 cols)
    const int m0   = blockIdx.x * 128;
    const int j0   = blockIdx.y * 128;

    // Precompute per-thread cp.async src/dst offsets (constant over kc).
    uint32_t doff[8];
    uint32_t soff[8];
    #pragma unroll
    for (int i = 0; i < 8; i++) {
        int cid = tid + i * 256;
        if (cid < 1024) {                 // A rows
            int r = cid >> 3, sub = cid & 7;
            int gr = m0 + r; if (gr >= NN) gr = NN - 1;
            doff[i] = tile_off(r, sub);
            soff[i] = (uint32_t)gr * 1024u + sub * 16u;
        } else {                          // B rows
            int c = cid - 1024;
            int r = c >> 3, sub = c & 7;
            doff[i] = B_REGION + tile_off(r, sub);
            soff[i] = (uint32_t)(j0 + r) * 1024u + sub * 16u;
        }
    }
    const char* zb = (const char*)g_zp;
    const char* wb = (const char*)g_wp;

    // Prologue: chunks 0,1 into stages 0,1
    #pragma unroll
    for (int pc = 0; pc < 2; pc++) {
        #pragma unroll
        for (int i = 0; i < 8; i++)
            cp16(sbase + pc * 16384 + doff[i], (i < 4 ? zb : wb) + soff[i] + pc * 128);
        asm volatile("cp.async.commit_group;" ::: "memory");
    }

    float acc[16][4];
    #pragma unroll
    for (int i = 0; i < 16; i++)
        #pragma unroll
        for (int q = 0; q < 4; q++) acc[i][q] = 0.f;

    int cur = 0;   // stage of chunk kc
    int pf  = 2;   // stage of chunk kc+2
    #pragma unroll 1
    for (int kc = 0; kc < 8; kc++) {
        if (kc < 7) asm volatile("cp.async.wait_group 1;" ::: "memory");
        else        asm volatile("cp.async.wait_group 0;" ::: "memory");
        __syncthreads();   // all warps: chunk kc resident; mma(kc-1) fully done

        if (kc < 6) {      // issue chunk kc+2 (overwrites stage used at kc-1)
            uint32_t stb = sbase + pf * 16384;
            #pragma unroll
            for (int i = 0; i < 8; i++)
                cp16(stb + doff[i], (i < 4 ? zb : wb) + soff[i] + (kc + 2) * 128);
            asm volatile("cp.async.commit_group;" ::: "memory");
        }

        const uint32_t Ab = sbase + cur * 16384;
        const uint32_t Bb = Ab + B_REGION;

        #pragma unroll
        for (int kk = 0; kk < 2; kk++) {
            const int c8h = kk * 2;
            const int c8l = 4 + kk * 2;
            uint32_t ah[4][4], al[4][4], bh[2][4], bl[2][4];
            #pragma unroll
            for (int mt = 0; mt < 4; mt++) {
                ldm4(ah[mt], ldm_addr(Ab, wm * 64 + mt * 16, c8h, lane));
                ldm4(al[mt], ldm_addr(Ab, wm * 64 + mt * 16, c8l, lane));
            }
            #pragma unroll
            for (int q = 0; q < 2; q++) {
                ldm4(bh[q], ldm_addr(Bb, wn * 32 + q * 16, c8h, lane));
                ldm4(bl[q], ldm_addr(Bb, wn * 32 + q * 16, c8l, lane));
            }
            #pragma unroll
            for (int mt = 0; mt < 4; mt++)
                #pragma unroll
                for (int nt = 0; nt < 4; nt++) {
                    uint32_t bh0 = bh[nt >> 1][nt & 1], bh1 = bh[nt >> 1][(nt & 1) + 2];
                    uint32_t bl0 = bl[nt >> 1][nt & 1], bl1 = bl[nt >> 1][(nt & 1) + 2];
                    float* cc = acc[mt * 4 + nt];
                    mma16816(cc, ah[mt], bh0, bh1);
                    mma16816(cc, ah[mt], bl0, bl1);
                    mma16816(cc, al[mt], bh0, bh1);
                }
        }
        cur = (cur == 2) ? 0 : cur + 1;
        pf  = (pf  == 2) ? 0 : pf  + 1;
    }

    // Epilogue: fp16 half2 stores (+ bias for cols < 256)
    const bool has_bias = (j0 < DD);
    #pragma unroll
    for (int nt = 0; nt < 4; nt++) {
        int colg = j0 + wn * 32 + nt * 8 + (lane & 3) * 2;
        float bv0 = 0.f, bv1 = 0.f;
        if (has_bias) { bv0 = __ldg(&b1[colg]); bv1 = __ldg(&b1[colg + 1]); }
        #pragma unroll
        for (int mt = 0; mt < 4; mt++) {
            float* cc = acc[mt * 4 + nt];
            int r0 = m0 + wm * 64 + mt * 16 + (lane >> 2);
            if (r0 < NN)
                *(__half2*)(g_ABh + (size_t)r0 * TWO_D + colg) =
                    __floats2half2_rn(cc[0] + bv0, cc[1] + bv1);
            if (r0 + 8 < NN)
                *(__half2*)(g_ABh + (size_t)(r0 + 8) * TWO_D + colg) =
                    __floats2half2_rn(cc[2] + bv0, cc[3] + bv1);
        }
    }
}

// ---------------------------------------------------------------------------
// Edge kernel: one warp per 2 edges per iteration (fp16 gathers).
//   out[e] = sum_d w2[d] * relu(A'[src][d] + B[dst][d]) + b2
// Lane covers d = 8*lane .. 8*lane+7 (one uint4 = 8 halves per row).
// ---------------------------------------------------------------------------
__device__ __forceinline__ float dot8(uint4 av, uint4 cv, float4 wA, float4 wB) {
    const __half2* ah = (const __half2*)&av;
    const __half2* ch = (const __half2*)&cv;
    float2 a0 = __half22float2(ah[0]), a1 = __half22float2(ah[1]);
    float2 a2 = __half22float2(ah[2]), a3 = __half22float2(ah[3]);
    float2 c0 = __half22float2(ch[0]), c1 = __half22float2(ch[1]);
    float2 c2 = __half22float2(ch[2]), c3 = __half22float2(ch[3]);
    float acc;
    acc  = wA.x * fmaxf(a0.x + c0.x, 0.f);
    acc += wA.y * fmaxf(a0.y + c0.y, 0.f);
    acc += wA.z * fmaxf(a1.x + c1.x, 0.f);
    acc += wA.w * fmaxf(a1.y + c1.y, 0.f);
    acc += wB.x * fmaxf(a2.x + c2.x, 0.f);
    acc += wB.y * fmaxf(a2.y + c2.y, 0.f);
    acc += wB.z * fmaxf(a3.x + c3.x, 0.f);
    acc += wB.w * fmaxf(a3.y + c3.y, 0.f);
    return acc;
}

__global__ __launch_bounds__(256)
void edge_kernel(const void* __restrict__ ei_raw,
                 const float* __restrict__ w2,
                 const float* __restrict__ b2,
                 float* __restrict__ out) {
    const int lane   = threadIdx.x & 31;
    const int warp   = (blockIdx.x * blockDim.x + threadIdx.x) >> 5;
    const int nwarps = (gridDim.x * blockDim.x) >> 5;
    const int is64   = g_idx_is64;

    const float4 wA = __ldg((const float4*)w2 + 2 * lane);
    const float4 wB = __ldg((const float4*)w2 + 2 * lane + 1);
    const float  b2v = __ldg(b2);

    const int*       ei32 = (const int*)ei_raw;
    const long long* ei64 = (const long long*)ei_raw;

    // EE is even, so e0+1 is always valid when striding by 2.
    for (int e0 = warp * 2; e0 < EE; e0 += nwarps * 2) {
        int s0, d0, s1, d1;
        if (is64) {
            s0 = (int)ei64[e0];     d0 = (int)ei64[EE + e0];
            s1 = (int)ei64[e0 + 1]; d1 = (int)ei64[EE + e0 + 1];
        } else {
            s0 = ei32[e0];     d0 = ei32[EE + e0];
            s1 = ei32[e0 + 1]; d1 = ei32[EE + e0 + 1];
        }
        uint4 a0 = __ldg((const uint4*)(g_ABh + (size_t)s0 * TWO_D) + lane);
        uint4 c0 = __ldg((const uint4*)(g_ABh + (size_t)d0 * TWO_D + DD) + lane);
        uint4 a1 = __ldg((const uint4*)(g_ABh + (size_t)s1 * TWO_D) + lane);
        uint4 c1 = __ldg((const uint4*)(g_ABh + (size_t)d1 * TWO_D + DD) + lane);

        float r0 = dot8(a0, c0, wA, wB);
        float r1 = dot8(a1, c1, wA, wB);

        #pragma unroll
        for (int o = 16; o > 0; o >>= 1) {
            r0 += __shfl_xor_sync(0xFFFFFFFFu, r0, o);
            r1 += __shfl_xor_sync(0xFFFFFFFFu, r1, o);
        }
        if (lane == 0) {
            out[e0]     = r0 + b2v;
            out[e0 + 1] = r1 + b2v;
        }
    }
}

// ---------------------------------------------------------------------------
extern "C" void kernel_launch(void* const* d_in, const int* in_sizes, int n_in,
                              void* d_out, int out_size) {
    const float* z  = (const float*)d_in[0];
    const void*  ei = d_in[1];
    const float* w1 = (const float*)d_in[2];
    const float* b1 = (const float*)d_in[3];
    const float* w2 = (const float*)d_in[4];
    const float* b2 = (const float*)d_in[5];
    float*       out = (float*)d_out;

    cudaFuncSetAttribute(node_gemm_mma, cudaFuncAttributeMaxDynamicSharedMemorySize,
                         SM_GEMM_TOTAL);

    detect_idx_kernel<<<1, 256>>>((const int*)ei);
    convert_z_kernel<<<4096, 256>>>(z);
    convert_w_kernel<<<(TWO_D * DD + 255) / 256, 256>>>(w1);

    dim3 ggrid((NN + 127) / 128, 4);   // 391 x 4
    node_gemm_mma<<<ggrid, 256, SM_GEMM_TOTAL>>>(b1);

    edge_kernel<<<2048, 256>>>(ei, w2, b2, out);
}